// round 16
// baseline (speedup 1.0000x reference)
#include <cuda_runtime.h>
#include <cuda_fp16.h>
#include <cstdint>

#define B_  2
#define T_  2048
#define S_  2048
#define H_  16
#define HD_ 64
#define DM_ 1024
#define LOG2E 1.4426950408889634f

// Scratch (allocation-free rule: __device__ globals)
__device__ unsigned g_xA[B_*T_*DM_/2];
__device__ unsigned g_yA[B_*S_*DM_/2];
__device__ unsigned g_oA[B_*T_*DM_/2];
__device__ unsigned g_WqB[DM_*DM_/2];
__device__ unsigned g_WkB[DM_*DM_/2];
__device__ unsigned g_WvB[DM_*DM_/2];
__device__ unsigned g_WoB[DM_*DM_/2];
__device__ unsigned g_Qf[2*1024*1024];
__device__ unsigned g_Kf[2*1024*1024];
__device__ unsigned g_Vf[2*1024*1024];
__device__ int      g_flags[1024];

// ---------------------------------------------------------------------------
// helpers
// ---------------------------------------------------------------------------
__device__ __forceinline__ unsigned packh2(float a, float b) {
    __half2 h = __floats2half2_rn(a, b);
    return *(unsigned*)&h;
}

__device__ __forceinline__ void mma16(float c[4], const unsigned a[4], const unsigned b[2]) {
    asm volatile(
        "mma.sync.aligned.m16n8k16.row.col.f32.f16.f16.f32 "
        "{%0,%1,%2,%3}, {%4,%5,%6,%7}, {%8,%9}, {%0,%1,%2,%3};"
        : "+f"(c[0]), "+f"(c[1]), "+f"(c[2]), "+f"(c[3])
        : "r"(a[0]), "r"(a[1]), "r"(a[2]), "r"(a[3]), "r"(b[0]), "r"(b[1]));
}

__device__ __forceinline__ uint32_t smem_u32(const void* p) {
    uint32_t a;
    asm("{ .reg .u64 t; cvta.to.shared.u64 t, %1; cvt.u32.u64 %0, t; }" : "=r"(a) : "l"(p));
    return a;
}

// (d0, d1) -> half2 -> 2^h2 packed (one MUFU op per TWO exps).
__device__ __forceinline__ unsigned exp2_h2(float d0, float d1) {
    unsigned h2, p2;
    asm("cvt.rn.f16x2.f32 %0, %1, %2;" : "=r"(h2) : "f"(d1), "f"(d0));
    asm("ex2.approx.f16x2 %0, %1;" : "=r"(p2) : "r"(h2));
    return p2;
}

#define CP_ASYNC16(dst, src) \
    asm volatile("cp.async.cg.shared.global [%0], [%1], 16;" :: "r"(dst), "l"(src) : "memory")
#define CP_COMMIT() asm volatile("cp.async.commit_group;" ::: "memory")
#define CP_WAIT1()  asm volatile("cp.async.wait_group 1;" ::: "memory")
#define CP_WAIT0()  asm volatile("cp.async.wait_group 0;" ::: "memory")

// ---------------------------------------------------------------------------
// prep kernel: convA(x), convA(y), convB(Wq/Wk/Wv) in PAIRED-nt layout.
// ---------------------------------------------------------------------------
__global__ __launch_bounds__(256)
void prep_kernel(const float* __restrict__ x,  const float* __restrict__ y,
                 const float* __restrict__ Wq, const float* __restrict__ Wk,
                 const float* __restrict__ Wv,
                 unsigned* __restrict__ xA, unsigned* __restrict__ yA,
                 unsigned* __restrict__ WqB, unsigned* __restrict__ WkB,
                 unsigned* __restrict__ WvB) {
    const int blk = blockIdx.x;
    const int tid = threadIdx.x;

    if (blk < 16384) {
        const float* src = (blk < 8192) ? x  : y;
        unsigned*    dst = (blk < 8192) ? xA : yA;
        size_t idx = (size_t)(blk & 8191) * 256 + tid;
        int row = (int)(idx >> 9);
        int c   = (int)(idx & 511) << 1;
        float2 v = *(const float2*)&src[(size_t)row * 1024 + c];
        int mt = row >> 4, rr = row & 15, g = rr & 7, hr = rr >> 3;
        int kt = c >> 4, cc = c & 15, tig = (cc >> 1) & 3, hc = cc >> 3;
        dst[((size_t)(mt * 64 + kt) << 7) + ((g * 4 + tig) << 2) + hr + 2 * hc] =
            packh2(v.x, v.y);
    } else {
        int r = blk - 16384;
        int w = r >> 11;
        const float* W   = (w == 0) ? Wq  : (w == 1) ? Wk  : Wv;
        unsigned*    dst = (w == 0) ? WqB : (w == 1) ? WkB : WvB;
        size_t idx = (size_t)(r & 2047) * 256 + tid;
        int n = (int)(idx & 1023);
        int k = (int)(idx >> 10) << 1;
        float lo = W[(size_t)k * 1024 + n];
        float hi = W[(size_t)(k + 1) * 1024 + n];
        int kt = k >> 4, kk = k & 15, hb = kk >> 3, tig = (kk & 7) >> 1;
        int nt = n >> 3, g = n & 7;
        int np = nt >> 1, odd = nt & 1;
        dst[((size_t)(kt * 64 + np) << 7) + ((g * 4 + tig) << 2) + odd * 2 + hb] =
            packh2(lo, hi);
    }
}

// ---------------------------------------------------------------------------
// GEMM mainloop, 512 THREADS (16 warps as 4x4): 128x128 tile, 32x32 per-warp
// microtile (acc 32 regs/thread -> 2 CTAs/SM = 32 warps/SM). K=64 chunks,
// 3 stages (96KB), 16 iterations, ONE barrier per iteration.
// ---------------------------------------------------------------------------
#define GT_SMEM 98304

#define GEMM_MAINLOOP(Af, Bf)                                                   \
    float acc[2][4][4];                                                         \
    _Pragma("unroll")                                                           \
    for (int i = 0; i < 2; i++)                                                 \
        _Pragma("unroll")                                                       \
        for (int j = 0; j < 4; j++)                                             \
            _Pragma("unroll")                                                   \
            for (int r = 0; r < 4; r++) acc[i][j][r] = 0.f;                     \
    auto issue = [&](int kb, int buf) {                                         \
        _Pragma("unroll")                                                       \
        for (int u = 0; u < 2; u++) {                                           \
            int i = tid + u * 512;                                              \
            int ti = i >> 5, mt = ti >> 2, kt = ti & 3;                         \
            size_t gt = (size_t)((bm >> 4) + mt) * 64 + kb * 4 + kt;            \
            CP_ASYNC16(sb + (buf * 8192 + ti * 128 + (i & 31) * 4) * 4,         \
                       (Af) + gt * 32 + (i & 31));                              \
            int blkb = i >> 5, bkt = blkb >> 3, npl = blkb & 7;                 \
            size_t gtb = (size_t)(kb * 4 + bkt) * 64 + (bn >> 4) + npl;         \
            CP_ASYNC16(sb + (buf * 8192 + 4096 + blkb * 128 + (i & 31) * 4) * 4,\
                       (Bf) + gtb * 32 + (i & 31));                             \
        }                                                                       \
        CP_COMMIT();                                                            \
    };                                                                          \
    issue(0, 0); issue(1, 1);                                                   \
    int bufc = 0;                                                               \
    for (int kb = 0; kb < 16; kb++) {                                           \
        if (kb < 15) { CP_WAIT1(); } else { CP_WAIT0(); }                       \
        __syncthreads();                                                        \
        if (kb + 2 < 16) {                                                      \
            int nb = bufc + 2; if (nb >= 3) nb -= 3;                            \
            issue(kb + 2, nb);                                                  \
        }                                                                       \
        const unsigned* aw = sm16 + bufc * 8192;                                \
        const unsigned* bw = aw + 4096;                                         \
        _Pragma("unroll")                                                       \
        for (int kt = 0; kt < 4; kt++) {                                        \
            unsigned a[2][4], b[4][2];                                          \
            _Pragma("unroll")                                                   \
            for (int p = 0; p < 2; p++) {                                       \
                uint4 bv = *(const uint4*)&bw[((kt * 8 + warp_n * 2 + p) << 7) + lane * 4]; \
                b[2 * p][0] = bv.x; b[2 * p][1] = bv.y;                         \
                b[2 * p + 1][0] = bv.z; b[2 * p + 1][1] = bv.w;                 \
            }                                                                   \
            _Pragma("unroll")                                                   \
            for (int im = 0; im < 2; im++)                                      \
                *(uint4*)a[im] = *(const uint4*)&aw[(((warp_m * 2 + im) * 4 + kt) << 7) + lane * 4]; \
            _Pragma("unroll")                                                   \
            for (int im = 0; im < 2; im++)                                      \
                _Pragma("unroll")                                               \
                for (int in_ = 0; in_ < 4; in_++)                               \
                    mma16(acc[im][in_], a[im], b[in_]);                         \
        }                                                                       \
        bufc++; if (bufc >= 3) bufc = 0;                                        \
    }

// ---------------------------------------------------------------------------
// Merged Q/K/V projection GEMM (512 thr) + overlapped Wo conv + maskflags.
// 1D grid, 2816 blocks:
//   [0,768)      GEMM tiles: op = bid>>8 (Q,K,V), tile = bid&255
//   [768,1792)   convB(Wo) -> WoB (paired layout, 512 thr/blk)
//   [1792,2816)  maskflags (512 thr/blk)
// ---------------------------------------------------------------------------
__global__ __launch_bounds__(512, 2)
void gemm_qkv(const uint4* __restrict__ xA, const uint4* __restrict__ yA,
              const uint4* __restrict__ WqB, const uint4* __restrict__ WkB,
              const uint4* __restrict__ WvB,
              unsigned* __restrict__ Qf, unsigned* __restrict__ Kf,
              unsigned* __restrict__ Vf,
              const float* __restrict__ cosb, const float* __restrict__ sinb,
              const float* __restrict__ Wo, unsigned* __restrict__ WoB,
              const float* __restrict__ mask, int* __restrict__ flags) {
    extern __shared__ unsigned sm16[];
    const int bid = blockIdx.x;
    const int tid = threadIdx.x;

    if (bid >= 768) {
        if (bid < 1792) {
            // convB(Wo) paired layout; 1024 blocks x 512 threads = 512K elems
            int r = bid - 768;
            size_t idx = (size_t)r * 512 + tid;
            int n = (int)(idx & 1023);
            int k = (int)(idx >> 10) << 1;
            float lo = Wo[(size_t)k * 1024 + n];
            float hi = Wo[(size_t)(k + 1) * 1024 + n];
            int kt = k >> 4, kk = k & 15, hb = kk >> 3, tg = (kk & 7) >> 1;
            int nt = n >> 3, g2 = n & 7;
            int np = nt >> 1, odd = nt & 1;
            WoB[((size_t)(kt * 64 + np) << 7) + ((g2 * 4 + tg) << 2) + odd * 2 + hb] =
                packh2(lo, hi);
        } else {
            // maskflags; 512 threads: 32 rows/pass x 4 passes
            int id = bid - 1792;
            int sbk = id & 31, tb = (id >> 5) & 15, b = id >> 9;
            const float* mb = mask + ((size_t)(b * 2048 + tb * 128)) * 2048 + sbk * 64;
            int nz = 0;
            int row0 = tid >> 4;             // 0..31
            int c4   = (tid & 15) << 2;
            #pragma unroll
            for (int r2 = 0; r2 < 4; r2++) {
                float4 v = *(const float4*)&mb[(size_t)(row0 + r2 * 32) * 2048 + c4];
                nz |= (v.x != 0.f) | (v.y != 0.f) | (v.z != 0.f) | (v.w != 0.f);
            }
            nz = __syncthreads_or(nz);
            if (tid == 0) flags[(b * 16 + tb) * 32 + sbk] = nz;
        }
        return;
    }

    const uint32_t sb = smem_u32(sm16);
    const int op   = bid >> 8;
    const int tile = bid & 255;
    const uint4* Af = (op == 0) ? xA : yA;
    const uint4* Bf = (op == 0) ? WqB : (op == 1) ? WkB : WvB;
    unsigned* Fout  = (op == 0) ? Qf  : (op == 1) ? Kf  : Vf;

    const int lane = tid & 31;
    const int wid  = tid >> 5;
    const int warp_m = wid >> 2;   // 0..3
    const int warp_n = wid & 3;    // 0..3
    const int g   = lane >> 2;
    const int tig = lane & 3;
    const int bm = (tile >> 3) * 128;
    const int bn = (tile & 7) * 128;

    GEMM_MAINLOOP(Af, Bf)

    if (op == 2) {
        // V: output row = s, col = h*64+d. Pair (s even, s odd) via shfl_xor 4.
        #pragma unroll
        for (int im = 0; im < 2; im++) {
            int row = bm + warp_m * 32 + im * 16;
            int b = row >> 11;
            int s = row & 2047;
            int kt = s >> 4;
            #pragma unroll
            for (int in_ = 0; in_ < 4; in_++) {
                #pragma unroll
                for (int e = 0; e < 2; e++) {
                    float v0 = acc[im][in_][e];
                    float v1 = acc[im][in_][2 + e];
                    float p0 = __shfl_xor_sync(0xffffffffu, v0, 4);
                    float p1 = __shfl_xor_sync(0xffffffffu, v1, 4);
                    if ((g & 1) == 0) {
                        int cc = bn + warp_n * 32 + in_ * 8 + tig * 2 + e;
                        int h = (cc >> 6) & 15, d = cc & 63;
                        int nt = d >> 3, dg = d & 7;
                        int bh = b * 16 + h;
                        size_t base = (size_t)bh * 65536 + ((size_t)kt << 9) +
                                      (nt << 6) + ((dg * 4 + (g >> 1)) << 1);
                        Fout[base]     = packh2(v0, p0);
                        Fout[base + 1] = packh2(v1, p1);
                    }
                }
            }
        }
    } else {
        const float QS = (op == 0) ? 0.125f * LOG2E : 1.0f;
        #pragma unroll
        for (int im = 0; im < 2; im++) {
            int row = bm + warp_m * 32 + im * 16 + g;
            int b = row >> 11, t = row & 2047;
            float v[4][4];
            #pragma unroll
            for (int j = 0; j < 4; j++)
                #pragma unroll
                for (int r = 0; r < 4; r++) v[j][r] = acc[im][j][r];
            if ((warp_n & 1) == 0) {   // d in [0,32): partial rope
                #pragma unroll
                for (int in0 = 0; in0 < 2; in0++) {
                    #pragma unroll
                    for (int e = 0; e < 2; e++) {
                        int d = in0 * 8 + tig * 2 + e;
                        float cl = cosb[t * 16 + d],       sl = sinb[t * 16 + d];
                        float ch = cosb[(t + 8) * 16 + d], sh = sinb[(t + 8) * 16 + d];
                        float x1 = v[in0][e],     x2 = v[in0 + 2][e];
                        v[in0][e]       = x1 * cl - x2 * sl;
                        v[in0 + 2][e]   = x2 * cl + x1 * sl;
                        float y1 = v[in0][2 + e], y2 = v[in0 + 2][2 + e];
                        v[in0][2 + e]     = y1 * ch - y2 * sh;
                        v[in0 + 2][2 + e] = y2 * ch + y1 * sh;
                    }
                }
            }
            #pragma unroll
            for (int p = 0; p < 2; p++) {
                int in0 = 2 * p, in1 = 2 * p + 1;
                int cc = bn + warp_n * 32 + in0 * 8;
                int h = (cc >> 6) & 15, d = cc & 63, kt = d >> 4;
                int bh = b * 16 + h;
                if (op == 0) {
                    int mt = t >> 4;
                    uint4 w;
                    w.x = packh2(v[in0][0] * QS, v[in0][1] * QS);
                    w.y = packh2(v[in0][2] * QS, v[in0][3] * QS);
                    w.z = packh2(v[in1][0] * QS, v[in1][1] * QS);
                    w.w = packh2(v[in1][2] * QS, v[in1][3] * QS);
                    *(uint4*)&Fout[(size_t)bh * 65536 + ((size_t)(mt * 4 + kt) << 7) + lane * 4] = w;
                } else {
                    int nt = t >> 3;
                    size_t base = (size_t)bh * 65536 + ((size_t)nt << 8) + (kt << 6) + (g * 4 + tig) * 2;
                    *(uint2*)&Fout[base] =
                        make_uint2(packh2(v[in0][0], v[in0][1]), packh2(v[in1][0], v[in1][1]));
                    *(uint2*)&Fout[base + 256] =
                        make_uint2(packh2(v[in0][2], v[in0][3]), packh2(v[in1][2], v[in1][3]));
                }
            }
        }
    }
}

// ---------------------------------------------------------------------------
// Output GEMM (512 thr): oA frags @ WoB frags (paired layout) -> fp32 out.
// ---------------------------------------------------------------------------
__global__ __launch_bounds__(512, 2)
void gemm_out(const uint4* __restrict__ Af, const uint4* __restrict__ Bf,
              float* __restrict__ C) {
    extern __shared__ unsigned sm16[];
    const uint32_t sb = smem_u32(sm16);
    const int tid  = threadIdx.x;
    const int lane = tid & 31;
    const int wid  = tid >> 5;
    const int warp_m = wid >> 2;
    const int warp_n = wid & 3;
    const int g   = lane >> 2;
    const int tig = lane & 3;
    const int bm = blockIdx.y * 128;
    const int bn = blockIdx.x * 128;

    GEMM_MAINLOOP(Af, Bf)

    #pragma unroll
    for (int im = 0; im < 2; im++) {
        int r0 = bm + warp_m * 32 + im * 16 + g;
        #pragma unroll
        for (int in_ = 0; in_ < 4; in_++) {
            int cc = bn + warp_n * 32 + in_ * 8 + tig * 2;
            *(float2*)&C[(size_t)r0 * 1024 + cc]       = make_float2(acc[im][in_][0], acc[im][in_][1]);
            *(float2*)&C[(size_t)(r0 + 8) * 1024 + cc] = make_float2(acc[im][in_][2], acc[im][in_][3]);
        }
    }
}

// ---------------------------------------------------------------------------
// Fused flash attention (round-14 proven, UNCHANGED): unshifted base-2
// softmax, 128-key stages, 3-stage cp.async (96KB), Q/P register-resident.
// ---------------------------------------------------------------------------
#define AT_SMEM (24576 * 4)

__global__ __launch_bounds__(256, 2)
void attn_f16(const uint4* __restrict__ Qf, const uint4* __restrict__ Kf,
              const uint4* __restrict__ Vf, const float* __restrict__ mask,
              const int* __restrict__ flags, unsigned* __restrict__ Of) {
    extern __shared__ unsigned sma[];
    const uint32_t sb = smem_u32(sma);
    const int tid  = threadIdx.x;
    const int lane = tid & 31;
    const int wid  = tid >> 5;
    const int g    = lane >> 2;
    const int tig  = lane & 3;
    const int tb   = blockIdx.x;
    const int h    = blockIdx.y;
    const int b    = blockIdx.z;
    const int t0   = tb * 128;
    const int bh   = b * 16 + h;

    auto issueKV = [&](int s0, int buf) {
        size_t kb = (size_t)bh * 16384 + (size_t)(s0 >> 3) * 64;
        size_t vb = (size_t)bh * 16384 + (size_t)(s0 >> 4) * 128;
        #pragma unroll
        for (int u = 0; u < 4; u++) {
            int c = tid + u * 256;
            CP_ASYNC16(sb + (buf * 8192 + c * 4) * 4,        Kf + kb + c);
            CP_ASYNC16(sb + (buf * 8192 + 4096 + c * 4) * 4, Vf + vb + c);
        }
        CP_COMMIT();
    };
    issueKV(0, 0);
    issueKV(128, 1);

    unsigned qr[4][4];
    {
        int mt = (t0 >> 4) + wid;
        #pragma unroll
        for (int kt = 0; kt < 4; kt++)
            *(uint4*)qr[kt] = Qf[(size_t)bh * 16384 + (size_t)(mt * 4 + kt) * 32 + lane];
    }

    float l_[2] = {0.f, 0.f};
    float acc[8][4];
    #pragma unroll
    for (int nt = 0; nt < 8; nt++)
        #pragma unroll
        for (int r = 0; r < 4; r++) acc[nt][r] = 0.f;

    const int nT = S_ / 128;   // 16
    int bufc = 0;
    for (int i = 0; i < nT; i++) {
        if (i + 1 < nT) { CP_WAIT1(); } else { CP_WAIT0(); }
        __syncthreads();
        if (i + 2 < nT) {
            int nb = bufc + 2; if (nb >= 3) nb -= 3;
            issueKV((i + 2) * 128, nb);
        }
        const unsigned* stage = sma + bufc * 8192;

        #pragma unroll
        for (int j = 0; j < 2; j++) {
            const unsigned* kw = stage + j * 2048;
            const unsigned* vw = stage + 4096 + j * 2048;
            const int sblk = i * 2 + j;

            float sc[8][4];
            int mz = __ldg(&flags[(b * 16 + tb) * 32 + sblk]);
            if (mz) {
                const float* mr0 = &mask[((size_t)b * T_ + t0 + wid * 16 + g) * S_ + sblk * 64];
                const float* mr1 = mr0 + 8 * S_;
                #pragma unroll
                for (int nt = 0; nt < 8; nt++) {
                    float2 m0 = *(const float2*)&mr0[nt * 8 + 2 * tig];
                    float2 m1 = *(const float2*)&mr1[nt * 8 + 2 * tig];
                    sc[nt][0] = m0.x * LOG2E; sc[nt][1] = m0.y * LOG2E;
                    sc[nt][2] = m1.x * LOG2E; sc[nt][3] = m1.y * LOG2E;
                }
            } else {
                #pragma unroll
                for (int nt = 0; nt < 8; nt++)
                    #pragma unroll
                    for (int r = 0; r < 4; r++) sc[nt][r] = 0.f;
            }

            #pragma unroll
            for (int kt = 0; kt < 4; kt++) {
                #pragma unroll
                for (int nt = 0; nt < 8; nt++) {
                    unsigned bb[2];
                    *(uint2*)bb = *(const uint2*)&kw[((nt * 4 + kt) << 6) + lane * 2];
                    mma16(sc[nt], qr[kt], bb);
                }
            }

            unsigned pu[8][2];
            #pragma unroll
            for (int e = 0; e < 2; e++) {
                #pragma unroll
                for (int nt = 0; nt < 8; nt++) {
                    unsigned p2 = exp2_h2(sc[nt][2 * e], sc[nt][2 * e + 1]);
                    pu[nt][e] = p2;
                    float2 pf = __half22float2(*(__half2*)&p2);
                    l_[e] += pf.x + pf.y;
                }
            }

            #pragma unroll
            for (int kt = 0; kt < 4; kt++) {
                unsigned a[4];
                a[0] = pu[2 * kt][0];
                a[1] = pu[2 * kt][1];
                a[2] = pu[2 * kt + 1][0];
                a[3] = pu[2 * kt + 1][1];
                #pragma unroll
                for (int nt = 0; nt < 8; nt++) {
                    unsigned bb[2];
                    *(uint2*)bb = *(const uint2*)&vw[((kt * 8 + nt) << 6) + lane * 2];
                    mma16(acc[nt], a, bb);
                }
            }
        }
        bufc++; if (bufc >= 3) bufc = 0;
    }

    #pragma unroll
    for (int e = 0; e < 2; e++) {
        l_[e] += __shfl_xor_sync(0xffffffffu, l_[e], 1);
        l_[e] += __shfl_xor_sync(0xffffffffu, l_[e], 2);
    }

    float inv0 = 1.f / l_[0];
    float inv1 = 1.f / l_[1];
    int mt_g = (b * 2048 + t0 + wid * 16) >> 4;
    #pragma unroll
    for (int kt = 0; kt < 4; kt++) {
        int nt0 = 2 * kt, nt1 = nt0 + 1;
        uint4 w;
        w.x = packh2(acc[nt0][0] * inv0, acc[nt0][1] * inv0);
        w.y = packh2(acc[nt0][2] * inv1, acc[nt0][3] * inv1);
        w.z = packh2(acc[nt1][0] * inv0, acc[nt1][1] * inv0);
        w.w = packh2(acc[nt1][2] * inv1, acc[nt1][3] * inv1);
        int kt_g = h * 4 + kt;
        *(uint4*)&Of[((size_t)(mt_g * 64 + kt_g) << 7) + lane * 4] = w;
    }
}

// ---------------------------------------------------------------------------
extern "C" void kernel_launch(void* const* d_in, const int* in_sizes, int n_in,
                              void* d_out, int out_size) {
    const float* x    = (const float*)d_in[0];
    const float* y    = (const float*)d_in[1];
    const float* cosb = (const float*)d_in[2];
    const float* sinb = (const float*)d_in[3];
    const float* mask = (const float*)d_in[4];
    const float* Wq   = (const float*)d_in[5];
    const float* Wk   = (const float*)d_in[6];
    const float* Wv   = (const float*)d_in[7];
    const float* Wo   = (const float*)d_in[8];
    float* out = (float*)d_out;

    void *pxA, *pyA, *poA, *pWq, *pWk, *pWv, *pWo, *pQf, *pKf, *pVf, *pfl;
    cudaGetSymbolAddress(&pxA, g_xA);
    cudaGetSymbolAddress(&pyA, g_yA);
    cudaGetSymbolAddress(&poA, g_oA);
    cudaGetSymbolAddress(&pWq, g_WqB);
    cudaGetSymbolAddress(&pWk, g_WkB);
    cudaGetSymbolAddress(&pWv, g_WvB);
    cudaGetSymbolAddress(&pWo, g_WoB);
    cudaGetSymbolAddress(&pQf, g_Qf);
    cudaGetSymbolAddress(&pKf, g_Kf);
    cudaGetSymbolAddress(&pVf, g_Vf);
    cudaGetSymbolAddress(&pfl, g_flags);

    cudaFuncSetAttribute(gemm_qkv, cudaFuncAttributeMaxDynamicSharedMemorySize, GT_SMEM);
    cudaFuncSetAttribute(gemm_out, cudaFuncAttributeMaxDynamicSharedMemorySize, GT_SMEM);
    cudaFuncSetAttribute(attn_f16, cudaFuncAttributeMaxDynamicSharedMemorySize, AT_SMEM);

    prep_kernel<<<22528, 256>>>(x, y, Wq, Wk, Wv,
                                (unsigned*)pxA, (unsigned*)pyA,
                                (unsigned*)pWq, (unsigned*)pWk, (unsigned*)pWv);

    gemm_qkv<<<2816, 512, GT_SMEM>>>(
        (const uint4*)pxA, (const uint4*)pyA,
        (const uint4*)pWq, (const uint4*)pWk, (const uint4*)pWv,
        (unsigned*)pQf, (unsigned*)pKf, (unsigned*)pVf, cosb, sinb,
        Wo, (unsigned*)pWo, mask, (int*)pfl);

    attn_f16<<<dim3(T_ / 128, H_, B_), 256, AT_SMEM>>>(
        (const uint4*)pQf, (const uint4*)pKf, (const uint4*)pVf,
        mask, (const int*)pfl, (unsigned*)poA);

    gemm_out<<<dim3(8, 32), 512, GT_SMEM>>>(
        (const uint4*)poA, (const uint4*)pWo, out);
}

// round 17
// speedup vs baseline: 1.0380x; 1.0380x over previous
#include <cuda_runtime.h>
#include <cuda_fp16.h>
#include <cstdint>

#define B_  2
#define T_  2048
#define S_  2048
#define H_  16
#define HD_ 64
#define DM_ 1024
#define LOG2E 1.4426950408889634f

// Scratch (allocation-free rule: __device__ globals)
__device__ unsigned g_xA[B_*T_*DM_/2];
__device__ unsigned g_yA[B_*S_*DM_/2];
__device__ unsigned g_oA[B_*T_*DM_/2];
__device__ unsigned g_WqB[DM_*DM_/2];
__device__ unsigned g_WkB[DM_*DM_/2];
__device__ unsigned g_WvB[DM_*DM_/2];
__device__ unsigned g_WoB[DM_*DM_/2];
__device__ unsigned g_Qf[2*1024*1024];
__device__ unsigned g_Kf[2*1024*1024];
__device__ unsigned g_Vf[2*1024*1024];
__device__ int      g_flags[1024];

// ---------------------------------------------------------------------------
// helpers
// ---------------------------------------------------------------------------
__device__ __forceinline__ unsigned packh2(float a, float b) {
    __half2 h = __floats2half2_rn(a, b);
    return *(unsigned*)&h;
}

__device__ __forceinline__ void mma16(float c[4], const unsigned a[4], const unsigned b[2]) {
    asm volatile(
        "mma.sync.aligned.m16n8k16.row.col.f32.f16.f16.f32 "
        "{%0,%1,%2,%3}, {%4,%5,%6,%7}, {%8,%9}, {%0,%1,%2,%3};"
        : "+f"(c[0]), "+f"(c[1]), "+f"(c[2]), "+f"(c[3])
        : "r"(a[0]), "r"(a[1]), "r"(a[2]), "r"(a[3]), "r"(b[0]), "r"(b[1]));
}

__device__ __forceinline__ uint32_t smem_u32(const void* p) {
    uint32_t a;
    asm("{ .reg .u64 t; cvta.to.shared.u64 t, %1; cvt.u32.u64 %0, t; }" : "=r"(a) : "l"(p));
    return a;
}

// (d0, d1) -> half2 -> 2^h2 packed (one MUFU op per TWO exps).
__device__ __forceinline__ unsigned exp2_h2(float d0, float d1) {
    unsigned h2, p2;
    asm("cvt.rn.f16x2.f32 %0, %1, %2;" : "=r"(h2) : "f"(d1), "f"(d0));
    asm("ex2.approx.f16x2 %0, %1;" : "=r"(p2) : "r"(h2));
    return p2;
}

#define CP_ASYNC16(dst, src) \
    asm volatile("cp.async.cg.shared.global [%0], [%1], 16;" :: "r"(dst), "l"(src) : "memory")
#define CP_COMMIT() asm volatile("cp.async.commit_group;" ::: "memory")
#define CP_WAIT1()  asm volatile("cp.async.wait_group 1;" ::: "memory")
#define CP_WAIT0()  asm volatile("cp.async.wait_group 0;" ::: "memory")

// ---------------------------------------------------------------------------
// prep kernel: convA(x), convA(y), convB(Wq/Wk/Wv) in PAIRED-nt layout.
// ---------------------------------------------------------------------------
__global__ __launch_bounds__(256)
void prep_kernel(const float* __restrict__ x,  const float* __restrict__ y,
                 const float* __restrict__ Wq, const float* __restrict__ Wk,
                 const float* __restrict__ Wv,
                 unsigned* __restrict__ xA, unsigned* __restrict__ yA,
                 unsigned* __restrict__ WqB, unsigned* __restrict__ WkB,
                 unsigned* __restrict__ WvB) {
    const int blk = blockIdx.x;
    const int tid = threadIdx.x;

    if (blk < 16384) {
        const float* src = (blk < 8192) ? x  : y;
        unsigned*    dst = (blk < 8192) ? xA : yA;
        size_t idx = (size_t)(blk & 8191) * 256 + tid;
        int row = (int)(idx >> 9);
        int c   = (int)(idx & 511) << 1;
        float2 v = *(const float2*)&src[(size_t)row * 1024 + c];
        int mt = row >> 4, rr = row & 15, g = rr & 7, hr = rr >> 3;
        int kt = c >> 4, cc = c & 15, tig = (cc >> 1) & 3, hc = cc >> 3;
        dst[((size_t)(mt * 64 + kt) << 7) + ((g * 4 + tig) << 2) + hr + 2 * hc] =
            packh2(v.x, v.y);
    } else {
        int r = blk - 16384;
        int w = r >> 11;
        const float* W   = (w == 0) ? Wq  : (w == 1) ? Wk  : Wv;
        unsigned*    dst = (w == 0) ? WqB : (w == 1) ? WkB : WvB;
        size_t idx = (size_t)(r & 2047) * 256 + tid;
        int n = (int)(idx & 1023);
        int k = (int)(idx >> 10) << 1;
        float lo = W[(size_t)k * 1024 + n];
        float hi = W[(size_t)(k + 1) * 1024 + n];
        int kt = k >> 4, kk = k & 15, hb = kk >> 3, tig = (kk & 7) >> 1;
        int nt = n >> 3, g = n & 7;
        int np = nt >> 1, odd = nt & 1;
        dst[((size_t)(kt * 64 + np) << 7) + ((g * 4 + tig) << 2) + odd * 2 + hb] =
            packh2(lo, hi);
    }
}

// ---------------------------------------------------------------------------
// GEMM mainloop (round-15 proven): 256 thr, 128x128 tile, K=64 chunks,
// 3 stages (96KB), 16 iterations, ONE barrier per iteration, paired-nt B.
// ---------------------------------------------------------------------------
#define GT_SMEM 98304

#define GEMM_MAINLOOP(Af, Bf)                                                   \
    float acc[4][4][4];                                                         \
    _Pragma("unroll")                                                           \
    for (int i = 0; i < 4; i++)                                                 \
        _Pragma("unroll")                                                       \
        for (int j = 0; j < 4; j++)                                             \
            _Pragma("unroll")                                                   \
            for (int r = 0; r < 4; r++) acc[i][j][r] = 0.f;                     \
    auto issue = [&](int kb, int buf) {                                         \
        _Pragma("unroll")                                                       \
        for (int u = 0; u < 4; u++) {                                           \
            int i = tid + u * 256;                                              \
            int ti = i >> 5, mt = ti >> 2, kt = ti & 3;                         \
            size_t gt = (size_t)((bm >> 4) + mt) * 64 + kb * 4 + kt;            \
            CP_ASYNC16(sb + (buf * 8192 + ti * 128 + (i & 31) * 4) * 4,         \
                       (Af) + gt * 32 + (i & 31));                              \
            int blkb = i >> 5, bkt = blkb >> 3, npl = blkb & 7;                 \
            size_t gtb = (size_t)(kb * 4 + bkt) * 64 + (bn >> 4) + npl;         \
            CP_ASYNC16(sb + (buf * 8192 + 4096 + blkb * 128 + (i & 31) * 4) * 4,\
                       (Bf) + gtb * 32 + (i & 31));                             \
        }                                                                       \
        CP_COMMIT();                                                            \
    };                                                                          \
    issue(0, 0); issue(1, 1);                                                   \
    int bufc = 0;                                                               \
    for (int kb = 0; kb < 16; kb++) {                                           \
        if (kb < 15) { CP_WAIT1(); } else { CP_WAIT0(); }                       \
        __syncthreads();                                                        \
        if (kb + 2 < 16) {                                                      \
            int nb = bufc + 2; if (nb >= 3) nb -= 3;                            \
            issue(kb + 2, nb);                                                  \
        }                                                                       \
        const unsigned* aw = sm16 + bufc * 8192;                                \
        const unsigned* bw = aw + 4096;                                         \
        _Pragma("unroll")                                                       \
        for (int kt = 0; kt < 4; kt++) {                                        \
            unsigned a[4][4], b[4][2];                                          \
            _Pragma("unroll")                                                   \
            for (int p = 0; p < 2; p++) {                                       \
                uint4 bv = *(const uint4*)&bw[((kt * 8 + warp_n * 2 + p) << 7) + lane * 4]; \
                b[2 * p][0] = bv.x; b[2 * p][1] = bv.y;                         \
                b[2 * p + 1][0] = bv.z; b[2 * p + 1][1] = bv.w;                 \
            }                                                                   \
            _Pragma("unroll")                                                   \
            for (int im = 0; im < 4; im++)                                      \
                *(uint4*)a[im] = *(const uint4*)&aw[(((warp_m * 4 + im) * 4 + kt) << 7) + lane * 4]; \
            _Pragma("unroll")                                                   \
            for (int im = 0; im < 4; im++)                                      \
                _Pragma("unroll")                                               \
                for (int in_ = 0; in_ < 4; in_++)                               \
                    mma16(acc[im][in_], a[im], b[in_]);                         \
        }                                                                       \
        bufc++; if (bufc >= 3) bufc = 0;                                        \
    }

// ---------------------------------------------------------------------------
// Merged Q/K/V projection GEMM + overlapped Wo conversion + maskflags.
// 1D grid, 3840 blocks (256 thr):
//   [0,768) GEMM | [768,2816) convB(Wo) | [2816,3840) maskflags
// ---------------------------------------------------------------------------
__global__ __launch_bounds__(256, 2)
void gemm_qkv(const uint4* __restrict__ xA, const uint4* __restrict__ yA,
              const uint4* __restrict__ WqB, const uint4* __restrict__ WkB,
              const uint4* __restrict__ WvB,
              unsigned* __restrict__ Qf, unsigned* __restrict__ Kf,
              unsigned* __restrict__ Vf,
              const float* __restrict__ cosb, const float* __restrict__ sinb,
              const float* __restrict__ Wo, unsigned* __restrict__ WoB,
              const float* __restrict__ mask, int* __restrict__ flags) {
    extern __shared__ unsigned sm16[];
    const int bid = blockIdx.x;
    const int tid = threadIdx.x;

    if (bid >= 768) {
        if (bid < 2816) {
            int r = bid - 768;
            size_t idx = (size_t)r * 256 + tid;
            int n = (int)(idx & 1023);
            int k = (int)(idx >> 10) << 1;
            float lo = Wo[(size_t)k * 1024 + n];
            float hi = Wo[(size_t)(k + 1) * 1024 + n];
            int kt = k >> 4, kk = k & 15, hb = kk >> 3, tg = (kk & 7) >> 1;
            int nt = n >> 3, g2 = n & 7;
            int np = nt >> 1, odd = nt & 1;
            WoB[((size_t)(kt * 64 + np) << 7) + ((g2 * 4 + tg) << 2) + odd * 2 + hb] =
                packh2(lo, hi);
        } else {
            int id = bid - 2816;
            int sbk = id & 31, tb = (id >> 5) & 15, b = id >> 9;
            const float* mb = mask + ((size_t)(b * 2048 + tb * 128)) * 2048 + sbk * 64;
            int nz = 0;
            int row0 = tid >> 4;
            int c4   = (tid & 15) << 2;
            #pragma unroll
            for (int r2 = 0; r2 < 8; r2++) {
                float4 v = *(const float4*)&mb[(size_t)(row0 + r2 * 16) * 2048 + c4];
                nz |= (v.x != 0.f) | (v.y != 0.f) | (v.z != 0.f) | (v.w != 0.f);
            }
            nz = __syncthreads_or(nz);
            if (tid == 0) flags[(b * 16 + tb) * 32 + sbk] = nz;
        }
        return;
    }

    const uint32_t sb = smem_u32(sm16);
    const int op   = bid >> 8;
    const int tile = bid & 255;
    const uint4* Af = (op == 0) ? xA : yA;
    const uint4* Bf = (op == 0) ? WqB : (op == 1) ? WkB : WvB;
    unsigned* Fout  = (op == 0) ? Qf  : (op == 1) ? Kf  : Vf;

    const int lane = tid & 31;
    const int wid  = tid >> 5;
    const int warp_m = wid >> 2;
    const int warp_n = wid & 3;
    const int g   = lane >> 2;
    const int tig = lane & 3;
    const int bm = (tile >> 3) * 128;
    const int bn = (tile & 7) * 128;

    GEMM_MAINLOOP(Af, Bf)

    if (op == 2) {
        #pragma unroll
        for (int im = 0; im < 4; im++) {
            int row = bm + warp_m * 64 + im * 16;
            int b = row >> 11;
            int s = row & 2047;
            int kt = s >> 4;
            #pragma unroll
            for (int in_ = 0; in_ < 4; in_++) {
                #pragma unroll
                for (int e = 0; e < 2; e++) {
                    float v0 = acc[im][in_][e];
                    float v1 = acc[im][in_][2 + e];
                    float p0 = __shfl_xor_sync(0xffffffffu, v0, 4);
                    float p1 = __shfl_xor_sync(0xffffffffu, v1, 4);
                    if ((g & 1) == 0) {
                        int cc = bn + warp_n * 32 + in_ * 8 + tig * 2 + e;
                        int h = (cc >> 6) & 15, d = cc & 63;
                        int nt = d >> 3, dg = d & 7;
                        int bh = b * 16 + h;
                        size_t base = (size_t)bh * 65536 + ((size_t)kt << 9) +
                                      (nt << 6) + ((dg * 4 + (g >> 1)) << 1);
                        Fout[base]     = packh2(v0, p0);
                        Fout[base + 1] = packh2(v1, p1);
                    }
                }
            }
        }
    } else {
        const float QS = (op == 0) ? 0.125f * LOG2E : 1.0f;
        #pragma unroll
        for (int im = 0; im < 4; im++) {
            int row = bm + warp_m * 64 + im * 16 + g;
            int b = row >> 11, t = row & 2047;
            float v[4][4];
            #pragma unroll
            for (int j = 0; j < 4; j++)
                #pragma unroll
                for (int r = 0; r < 4; r++) v[j][r] = acc[im][j][r];
            if ((warp_n & 1) == 0) {
                #pragma unroll
                for (int in0 = 0; in0 < 2; in0++) {
                    #pragma unroll
                    for (int e = 0; e < 2; e++) {
                        int d = in0 * 8 + tig * 2 + e;
                        float cl = cosb[t * 16 + d],       sl = sinb[t * 16 + d];
                        float ch = cosb[(t + 8) * 16 + d], sh = sinb[(t + 8) * 16 + d];
                        float x1 = v[in0][e],     x2 = v[in0 + 2][e];
                        v[in0][e]       = x1 * cl - x2 * sl;
                        v[in0 + 2][e]   = x2 * cl + x1 * sl;
                        float y1 = v[in0][2 + e], y2 = v[in0 + 2][2 + e];
                        v[in0][2 + e]     = y1 * ch - y2 * sh;
                        v[in0 + 2][2 + e] = y2 * ch + y1 * sh;
                    }
                }
            }
            #pragma unroll
            for (int p = 0; p < 2; p++) {
                int in0 = 2 * p, in1 = 2 * p + 1;
                int cc = bn + warp_n * 32 + in0 * 8;
                int h = (cc >> 6) & 15, d = cc & 63, kt = d >> 4;
                int bh = b * 16 + h;
                if (op == 0) {
                    int mt = t >> 4;
                    uint4 w;
                    w.x = packh2(v[in0][0] * QS, v[in0][1] * QS);
                    w.y = packh2(v[in0][2] * QS, v[in0][3] * QS);
                    w.z = packh2(v[in1][0] * QS, v[in1][1] * QS);
                    w.w = packh2(v[in1][2] * QS, v[in1][3] * QS);
                    *(uint4*)&Fout[(size_t)bh * 65536 + ((size_t)(mt * 4 + kt) << 7) + lane * 4] = w;
                } else {
                    int nt = t >> 3;
                    size_t base = (size_t)bh * 65536 + ((size_t)nt << 8) + (kt << 6) + (g * 4 + tig) * 2;
                    *(uint2*)&Fout[base] =
                        make_uint2(packh2(v[in0][0], v[in0][1]), packh2(v[in1][0], v[in1][1]));
                    *(uint2*)&Fout[base + 256] =
                        make_uint2(packh2(v[in0][2], v[in0][3]), packh2(v[in1][2], v[in1][3]));
                }
            }
        }
    }
}

// ---------------------------------------------------------------------------
// Output GEMM (256 thr): oA frags @ WoB frags (paired layout) -> fp32 out.
// ---------------------------------------------------------------------------
__global__ __launch_bounds__(256, 2)
void gemm_out(const uint4* __restrict__ Af, const uint4* __restrict__ Bf,
              float* __restrict__ C) {
    extern __shared__ unsigned sm16[];
    const uint32_t sb = smem_u32(sm16);
    const int tid  = threadIdx.x;
    const int lane = tid & 31;
    const int wid  = tid >> 5;
    const int warp_m = wid >> 2;
    const int warp_n = wid & 3;
    const int g   = lane >> 2;
    const int tig = lane & 3;
    const int bm = blockIdx.y * 128;
    const int bn = blockIdx.x * 128;

    GEMM_MAINLOOP(Af, Bf)

    #pragma unroll
    for (int im = 0; im < 4; im++) {
        int r0 = bm + warp_m * 64 + im * 16 + g;
        #pragma unroll
        for (int in_ = 0; in_ < 4; in_++) {
            int cc = bn + warp_n * 32 + in_ * 8 + tig * 2;
            *(float2*)&C[(size_t)r0 * 1024 + cc]       = make_float2(acc[im][in_][0], acc[im][in_][1]);
            *(float2*)&C[(size_t)(r0 + 8) * 1024 + cc] = make_float2(acc[im][in_][2], acc[im][in_][3]);
        }
    }
}

// ---------------------------------------------------------------------------
// Fused flash attention: unshifted base-2 softmax; the row-sum l is computed
// ON THE TENSOR PIPE via an extra mma against a ones-vector B fragment
// (deletes the cvt/fadd l-chain AND the final shfl reduction).
// 128-key stages, 3-stage cp.async (96KB), Q/P register-resident.
// ---------------------------------------------------------------------------
#define AT_SMEM (24576 * 4)

__global__ __launch_bounds__(256, 2)
void attn_f16(const uint4* __restrict__ Qf, const uint4* __restrict__ Kf,
              const uint4* __restrict__ Vf, const float* __restrict__ mask,
              const int* __restrict__ flags, unsigned* __restrict__ Of) {
    extern __shared__ unsigned sma[];
    const uint32_t sb = smem_u32(sma);
    const int tid  = threadIdx.x;
    const int lane = tid & 31;
    const int wid  = tid >> 5;
    const int g    = lane >> 2;
    const int tig  = lane & 3;
    const int tb   = blockIdx.x;
    const int h    = blockIdx.y;
    const int b    = blockIdx.z;
    const int t0   = tb * 128;
    const int bh   = b * 16 + h;

    auto issueKV = [&](int s0, int buf) {
        size_t kb = (size_t)bh * 16384 + (size_t)(s0 >> 3) * 64;
        size_t vb = (size_t)bh * 16384 + (size_t)(s0 >> 4) * 128;
        #pragma unroll
        for (int u = 0; u < 4; u++) {
            int c = tid + u * 256;
            CP_ASYNC16(sb + (buf * 8192 + c * 4) * 4,        Kf + kb + c);
            CP_ASYNC16(sb + (buf * 8192 + 4096 + c * 4) * 4, Vf + vb + c);
        }
        CP_COMMIT();
    };
    issueKV(0, 0);
    issueKV(128, 1);

    unsigned qr[4][4];
    {
        int mt = (t0 >> 4) + wid;
        #pragma unroll
        for (int kt = 0; kt < 4; kt++)
            *(uint4*)qr[kt] = Qf[(size_t)bh * 16384 + (size_t)(mt * 4 + kt) * 32 + lane];
    }

    // ones-vector B fragment for the l-sum mma (h1.0 packed twice)
    const unsigned bones[2] = {0x3C003C00u, 0x3C003C00u};
    float accl[4] = {0.f, 0.f, 0.f, 0.f};

    float acc[8][4];
    #pragma unroll
    for (int nt = 0; nt < 8; nt++)
        #pragma unroll
        for (int r = 0; r < 4; r++) acc[nt][r] = 0.f;

    const int nT = S_ / 128;   // 16
    int bufc = 0;
    for (int i = 0; i < nT; i++) {
        if (i + 1 < nT) { CP_WAIT1(); } else { CP_WAIT0(); }
        __syncthreads();
        if (i + 2 < nT) {
            int nb = bufc + 2; if (nb >= 3) nb -= 3;
            issueKV((i + 2) * 128, nb);
        }
        const unsigned* stage = sma + bufc * 8192;

        #pragma unroll
        for (int j = 0; j < 2; j++) {
            const unsigned* kw = stage + j * 2048;
            const unsigned* vw = stage + 4096 + j * 2048;
            const int sblk = i * 2 + j;

            float sc[8][4];
            int mz = __ldg(&flags[(b * 16 + tb) * 32 + sblk]);
            if (mz) {
                const float* mr0 = &mask[((size_t)b * T_ + t0 + wid * 16 + g) * S_ + sblk * 64];
                const float* mr1 = mr0 + 8 * S_;
                #pragma unroll
                for (int nt = 0; nt < 8; nt++) {
                    float2 m0 = *(const float2*)&mr0[nt * 8 + 2 * tig];
                    float2 m1 = *(const float2*)&mr1[nt * 8 + 2 * tig];
                    sc[nt][0] = m0.x * LOG2E; sc[nt][1] = m0.y * LOG2E;
                    sc[nt][2] = m1.x * LOG2E; sc[nt][3] = m1.y * LOG2E;
                }
            } else {
                #pragma unroll
                for (int nt = 0; nt < 8; nt++)
                    #pragma unroll
                    for (int r = 0; r < 4; r++) sc[nt][r] = 0.f;
            }

            #pragma unroll
            for (int kt = 0; kt < 4; kt++) {
                #pragma unroll
                for (int nt = 0; nt < 8; nt++) {
                    unsigned bb[2];
                    *(uint2*)bb = *(const uint2*)&kw[((nt * 4 + kt) << 6) + lane * 2];
                    mma16(sc[nt], qr[kt], bb);
                }
            }

            unsigned pu[8][2];
            #pragma unroll
            for (int e = 0; e < 2; e++) {
                #pragma unroll
                for (int nt = 0; nt < 8; nt++)
                    pu[nt][e] = exp2_h2(sc[nt][2 * e], sc[nt][2 * e + 1]);
            }

            // acc += P @ V, plus accl += P @ ones (row-sum on the tensor pipe)
            #pragma unroll
            for (int kt = 0; kt < 4; kt++) {
                unsigned a[4];
                a[0] = pu[2 * kt][0];
                a[1] = pu[2 * kt][1];
                a[2] = pu[2 * kt + 1][0];
                a[3] = pu[2 * kt + 1][1];
                #pragma unroll
                for (int nt = 0; nt < 8; nt++) {
                    unsigned bb[2];
                    *(uint2*)bb = *(const uint2*)&vw[((kt * 8 + nt) << 6) + lane * 2];
                    mma16(acc[nt], a, bb);
                }
                mma16(accl, a, bones);
            }
        }
        bufc++; if (bufc >= 3) bufc = 0;
    }

    // every lane's accl[0]/accl[2] already hold the full row sums
    float inv0 = 1.f / accl[0];
    float inv1 = 1.f / accl[2];
    int mt_g = (b * 2048 + t0 + wid * 16) >> 4;
    #pragma unroll
    for (int kt = 0; kt < 4; kt++) {
        int nt0 = 2 * kt, nt1 = nt0 + 1;
        uint4 w;
        w.x = packh2(acc[nt0][0] * inv0, acc[nt0][1] * inv0);
        w.y = packh2(acc[nt0][2] * inv1, acc[nt0][3] * inv1);
        w.z = packh2(acc[nt1][0] * inv0, acc[nt1][1] * inv0);
        w.w = packh2(acc[nt1][2] * inv1, acc[nt1][3] * inv1);
        int kt_g = h * 4 + kt;
        *(uint4*)&Of[((size_t)(mt_g * 64 + kt_g) << 7) + lane * 4] = w;
    }
}

// ---------------------------------------------------------------------------
extern "C" void kernel_launch(void* const* d_in, const int* in_sizes, int n_in,
                              void* d_out, int out_size) {
    const float* x    = (const float*)d_in[0];
    const float* y    = (const float*)d_in[1];
    const float* cosb = (const float*)d_in[2];
    const float* sinb = (const float*)d_in[3];
    const float* mask = (const float*)d_in[4];
    const float* Wq   = (const float*)d_in[5];
    const float* Wk   = (const float*)d_in[6];
    const float* Wv   = (const float*)d_in[7];
    const float* Wo   = (const float*)d_in[8];
    float* out = (float*)d_out;

    void *pxA, *pyA, *poA, *pWq, *pWk, *pWv, *pWo, *pQf, *pKf, *pVf, *pfl;
    cudaGetSymbolAddress(&pxA, g_xA);
    cudaGetSymbolAddress(&pyA, g_yA);
    cudaGetSymbolAddress(&poA, g_oA);
    cudaGetSymbolAddress(&pWq, g_WqB);
    cudaGetSymbolAddress(&pWk, g_WkB);
    cudaGetSymbolAddress(&pWv, g_WvB);
    cudaGetSymbolAddress(&pWo, g_WoB);
    cudaGetSymbolAddress(&pQf, g_Qf);
    cudaGetSymbolAddress(&pKf, g_Kf);
    cudaGetSymbolAddress(&pVf, g_Vf);
    cudaGetSymbolAddress(&pfl, g_flags);

    cudaFuncSetAttribute(gemm_qkv, cudaFuncAttributeMaxDynamicSharedMemorySize, GT_SMEM);
    cudaFuncSetAttribute(gemm_out, cudaFuncAttributeMaxDynamicSharedMemorySize, GT_SMEM);
    cudaFuncSetAttribute(attn_f16, cudaFuncAttributeMaxDynamicSharedMemorySize, AT_SMEM);

    prep_kernel<<<22528, 256>>>(x, y, Wq, Wk, Wv,
                                (unsigned*)pxA, (unsigned*)pyA,
                                (unsigned*)pWq, (unsigned*)pWk, (unsigned*)pWv);

    gemm_qkv<<<3840, 256, GT_SMEM>>>(
        (const uint4*)pxA, (const uint4*)pyA,
        (const uint4*)pWq, (const uint4*)pWk, (const uint4*)pWv,
        (unsigned*)pQf, (unsigned*)pKf, (unsigned*)pVf, cosb, sinb,
        Wo, (unsigned*)pWo, mask, (int*)pfl);

    attn_f16<<<dim3(T_ / 128, H_, B_), 256, AT_SMEM>>>(
        (const uint4*)pQf, (const uint4*)pKf, (const uint4*)pVf,
        mask, (const int*)pfl, (unsigned*)poA);

    gemm_out<<<dim3(8, 32), 256, GT_SMEM>>>(
        (const uint4*)poA, (const uint4*)pWo, out);
}